// round 5
// baseline (speedup 1.0000x reference)
#include <cuda_runtime.h>
#include <cuda_fp16.h>
#include <stdint.h>

#define BH_TOTAL 64
#define SEQ 4096
#define DIM 64
#define M2_DIM 512
#define QROWS 256

// SKS in e4m3 (scaled by sqrt(0.125*log2e)); STV in f16
__device__ __align__(16) uint8_t g_SKS8[(size_t)BH_TOTAL * M2_DIM * DIM];
__device__ __half g_STV[(size_t)BH_TOTAL * M2_DIM * DIM];

#define QK_SCALE 0.15014065f   // sqrt(0.125 * 1.44269504)

// ---------- helpers ----------
// 128-byte smem rows, 16-byte granules, XOR swizzle
static __device__ __forceinline__ uint32_t swz(int row, int g) {
    return (uint32_t)(row * 128 + ((g ^ (row & 7)) << 4));
}
// fp8 tiles: logical 64B rows packed 2-per-128B smem row. row = q/m index, kb = 16B granule (0..3)
static __device__ __forceinline__ uint32_t f8off(int row, int kb) {
    int srow = row >> 1;
    int g = ((row & 1) << 2) | kb;
    return (uint32_t)(srow * 128 + ((g ^ (srow & 7)) << 4));
}
static __device__ __forceinline__ void ldsm_x4(uint32_t& r0, uint32_t& r1, uint32_t& r2,
                                               uint32_t& r3, uint32_t addr) {
    asm volatile("ldmatrix.sync.aligned.m8n8.x4.shared.b16 {%0,%1,%2,%3}, [%4];"
                 : "=r"(r0), "=r"(r1), "=r"(r2), "=r"(r3) : "r"(addr));
}
static __device__ __forceinline__ void ldsm_x4_t(uint32_t& r0, uint32_t& r1, uint32_t& r2,
                                                 uint32_t& r3, uint32_t addr) {
    asm volatile("ldmatrix.sync.aligned.m8n8.x4.trans.shared.b16 {%0,%1,%2,%3}, [%4];"
                 : "=r"(r0), "=r"(r1), "=r"(r2), "=r"(r3) : "r"(addr));
}
static __device__ __forceinline__ void mma_fp8(float* c, const uint32_t* a,
                                               uint32_t b0, uint32_t b1) {
    asm volatile("mma.sync.aligned.m16n8k32.row.col.f32.e4m3.e4m3.f32 "
                 "{%0,%1,%2,%3}, {%4,%5,%6,%7}, {%8,%9}, {%0,%1,%2,%3};"
                 : "+f"(c[0]), "+f"(c[1]), "+f"(c[2]), "+f"(c[3])
                 : "r"(a[0]), "r"(a[1]), "r"(a[2]), "r"(a[3]), "r"(b0), "r"(b1));
}
static __device__ __forceinline__ void mma_f16(uint32_t& c0, uint32_t& c1,
                                               uint32_t a0, uint32_t a1, uint32_t a2, uint32_t a3,
                                               uint32_t b0, uint32_t b1) {
    asm volatile("mma.sync.aligned.m16n8k16.row.col.f16.f16.f16.f16 "
                 "{%0,%1}, {%2,%3,%4,%5}, {%6,%7}, {%0,%1};"
                 : "+r"(c0), "+r"(c1)
                 : "r"(a0), "r"(a1), "r"(a2), "r"(a3), "r"(b0), "r"(b1));
}
static __device__ __forceinline__ void cp16(uint32_t dst, const void* src) {
    asm volatile("cp.async.cg.shared.global [%0], [%1], 16;" :: "r"(dst), "l"(src));
}
#define CP_COMMIT() asm volatile("cp.async.commit_group;")
// pack 4 floats -> 4 e4m3 bytes (shared by Q and SKS paths: consistent byte order)
static __device__ __forceinline__ uint32_t pack_e4m3_4(float x0, float x1, float x2, float x3) {
    uint16_t lo, hi;
    asm("cvt.rn.satfinite.e4m3x2.f32 %0, %1, %2;" : "=h"(lo) : "f"(x1), "f"(x0));
    asm("cvt.rn.satfinite.e4m3x2.f32 %0, %1, %2;" : "=h"(hi) : "f"(x3), "f"(x2));
    return (uint32_t)lo | ((uint32_t)hi << 16);
}
static __device__ __forceinline__ uint32_t h2u(__half2 h) {
    return *reinterpret_cast<uint32_t*>(&h);
}

// ---------- prep: SKS (e4m3) + STV (f16) ----------
// SKS[bh][m][d2] = scale * sum_j K[bh][(m&7)*512 + j*64 + d2][m>>3]
// STV[bh][m][d]  = (1/8) sum_j V[bh][8m+j][d]
__global__ __launch_bounds__(256) void prep_kernel(const float* __restrict__ K,
                                                   const float* __restrict__ V) {
    __shared__ float acc[64][65];
    const int tid = threadIdx.x;
    const int mb = blockIdx.x;   // 0..7
    const int bh = blockIdx.y;   // 0..63

    // --- transpose-accumulate 512x64 K slab: acc[dk][d2] = sum over 8 strided rows ---
    const float* Kb = K + ((size_t)bh * SEQ + (size_t)mb * 512) * DIM;
    float a[16];
#pragma unroll
    for (int e = 0; e < 16; e++) a[e] = 0.f;
    for (int j = 0; j < 8; j++) {
#pragma unroll
        for (int e = 0; e < 16; e++) {
            int i = e * 256 + tid;
            int r = i >> 6, c = i & 63;
            a[e] += Kb[(size_t)(j * 64 + r) * DIM + c];
        }
    }
#pragma unroll
    for (int e = 0; e < 16; e++) {
        int i = e * 256 + tid;
        int r = i >> 6, c = i & 63;
        acc[c][r] = a[e];
    }
    __syncthreads();

    // SKS e4m3 write: thread t -> row dk = t>>2, 16 bytes at d2 = (t&3)*16
    {
        const int dk = tid >> 2;
        const int d2b = (tid & 3) * 16;
        uint8_t* dstS = g_SKS8 + (size_t)bh * M2_DIM * DIM + (size_t)(8 * dk + mb) * DIM + d2b;
        uint4 u;
        uint32_t w[4];
#pragma unroll
        for (int j = 0; j < 4; j++) {
            w[j] = pack_e4m3_4(acc[dk][d2b + 4 * j + 0] * QK_SCALE,
                               acc[dk][d2b + 4 * j + 1] * QK_SCALE,
                               acc[dk][d2b + 4 * j + 2] * QK_SCALE,
                               acc[dk][d2b + 4 * j + 3] * QK_SCALE);
        }
        u.x = w[0]; u.y = w[1]; u.z = w[2]; u.w = w[3];
        *reinterpret_cast<uint4*>(dstS) = u;
    }

    // --- STV: chunk mean of V (f16) ---
    const float* Vb = V + (size_t)bh * SEQ * DIM;
    __half* dstV = g_STV + (size_t)bh * M2_DIM * DIM;
#pragma unroll
    for (int e = 0; e < 16; e++) {
        int i = e * 256 + tid;
        int ml = i >> 6, d = i & 63;
        int m = mb * 64 + ml;
        float s = 0.f;
#pragma unroll
        for (int j = 0; j < 8; j++) s += Vb[(size_t)(m * 8 + j) * DIM + d];
        dstV[(size_t)m * DIM + d] = __float2half_rn(s * 0.125f);
    }
}

// ---------- fused sketch attention: fp8 GEMM1 + f16 GEMM2 ----------
// 256 q-rows/block, 8 warps, 32 rows/warp (2 groups of 16). m chunked 4x128.
__global__ __launch_bounds__(256, 2) void attn_kernel(const float* __restrict__ Q,
                                                      const float* __restrict__ V,
                                                      float* __restrict__ out) {
    extern __shared__ __align__(16) char smem[];
    const int tid = threadIdx.x;
    const int lane = tid & 31;
    const int warp = tid >> 5;
    const int bh = blockIdx.y;
    const int nblk = blockIdx.x * QROWS;

    const uint32_t sbase = (uint32_t)__cvta_generic_to_shared(smem);
    const uint32_t SQ  = sbase;               // 16 KB  Q fp8 (256 x 64B)
    const uint32_t KS0 = sbase + 16384;       // 8 KB   SKS fp8 chunk (128 x 64B)
    const uint32_t KS1 = sbase + 24576;
    const uint32_t TV0 = sbase + 32768;       // 16 KB  STV f16 chunk (128 x 128B)
    const uint32_t TV1 = sbase + 49152;       // total 64 KB

    const uint8_t* gKS = g_SKS8 + (size_t)bh * M2_DIM * DIM;
    const __half*  gTV = g_STV  + (size_t)bh * M2_DIM * DIM;

    auto load_chunk = [&](int c, uint32_t ksb, uint32_t tvb) {
        const char* srcK = (const char*)(gKS + (size_t)c * 128 * DIM);
        const uint4* srcV = reinterpret_cast<const uint4*>(gTV + (size_t)c * 128 * DIM);
#pragma unroll
        for (int k = 0; k < 2; k++) {         // 512 fp8 granules
            int gi = k * 256 + tid;
            int mr = gi >> 2, kb = gi & 3;
            cp16(ksb + f8off(mr, kb), srcK + gi * 16);
        }
#pragma unroll
        for (int k = 0; k < 4; k++) {         // 1024 f16 granules
            int gi = k * 256 + tid;
            int row = gi >> 3, g = gi & 7;
            cp16(tvb + swz(row, g), srcV + gi);
        }
    };

    load_chunk(0, KS0, TV0); CP_COMMIT();
    load_chunk(1, KS1, TV1); CP_COMMIT();

    // Q: fp32 -> e4m3 * QK_SCALE into swizzled smem
    {
        const float* Qb = Q + ((size_t)bh * SEQ + nblk) * DIM;
#pragma unroll
        for (int k = 0; k < 4; k++) {
            int gi = k * 256 + tid;           // 1024 granules of 16 e4m3
            int row = gi >> 2, kb = gi & 3;
            const float4* s4 = reinterpret_cast<const float4*>(Qb + (size_t)row * DIM + kb * 16);
            float4 f0 = s4[0], f1 = s4[1], f2 = s4[2], f3 = s4[3];
            uint4 u;
            u.x = pack_e4m3_4(f0.x * QK_SCALE, f0.y * QK_SCALE, f0.z * QK_SCALE, f0.w * QK_SCALE);
            u.y = pack_e4m3_4(f1.x * QK_SCALE, f1.y * QK_SCALE, f1.z * QK_SCALE, f1.w * QK_SCALE);
            u.z = pack_e4m3_4(f2.x * QK_SCALE, f2.y * QK_SCALE, f2.z * QK_SCALE, f2.w * QK_SCALE);
            u.w = pack_e4m3_4(f3.x * QK_SCALE, f3.y * QK_SCALE, f3.z * QK_SCALE, f3.w * QK_SCALE);
            *reinterpret_cast<uint4*>(smem + f8off(row, kb)) = u;
        }
    }
    __syncthreads();

    // Q A-frags (fp8 m16n8k32): per grp, 2 k32-tiles
    uint32_t qa[2][2][4];
#pragma unroll
    for (int grp = 0; grp < 2; grp++) {
#pragma unroll
        for (int kt = 0; kt < 2; kt++) {
            int row = warp * 32 + grp * 16 + ((lane >> 3) & 1) * 8 + (lane & 7);
            int kb = 2 * kt + ((lane >> 4) & 1);
            ldsm_x4(qa[grp][kt][0], qa[grp][kt][1], qa[grp][kt][2], qa[grp][kt][3],
                    SQ + f8off(row, kb));
        }
    }

    uint32_t o[2][8][2];
#pragma unroll
    for (int grp = 0; grp < 2; grp++)
#pragma unroll
        for (int t = 0; t < 8; t++) { o[grp][t][0] = 0u; o[grp][t][1] = 0u; }
    float rs[2][2] = {{0.f, 0.f}, {0.f, 0.f}};

#pragma unroll
    for (int c = 0; c < 4; c++) {
        if (c < 3) asm volatile("cp.async.wait_group 1;");
        else       asm volatile("cp.async.wait_group 0;");
        __syncthreads();
        const uint32_t ksb = (c & 1) ? KS1 : KS0;
        const uint32_t tvb = (c & 1) ? TV1 : TV0;

#pragma unroll
        for (int h = 0; h < 2; h++) {
            uint32_t pk[2][8][2];

            // ---- per grp: S = Q @ SKS_half^T (fp8, f32 accum), then exp2 -> f16 P ----
#pragma unroll
            for (int grp = 0; grp < 2; grp++) {
                float s[8][4];
#pragma unroll
                for (int i = 0; i < 8; i++) { s[i][0] = 0.f; s[i][1] = 0.f; s[i][2] = 0.f; s[i][3] = 0.f; }

#pragma unroll
                for (int kt = 0; kt < 2; kt++) {
#pragma unroll
                    for (int p = 0; p < 4; p++) {
                        int mr = h * 64 + p * 16 + ((lane >> 4) & 1) * 8 + (lane & 7);
                        int kb = 2 * kt + ((lane >> 3) & 1);
                        uint32_t b0, b1, b2, b3;
                        ldsm_x4(b0, b1, b2, b3, ksb + f8off(mr, kb));
                        mma_fp8(s[2 * p],     qa[grp][kt], b0, b1);
                        mma_fp8(s[2 * p + 1], qa[grp][kt], b2, b3);
                    }
                }

                // exp2 in f16x2 (logits already in log2 domain), rowsum in half2
                __half2 rh0 = __floats2half2_rn(0.f, 0.f);
                __half2 rh1 = rh0;
#pragma unroll
                for (int j = 0; j < 8; j++) {
                    __half2 h0 = __floats2half2_rn(s[j][0], s[j][1]);
                    __half2 h1 = __floats2half2_rn(s[j][2], s[j][3]);
                    __half2 e0 = h2exp2(h0);
                    __half2 e1 = h2exp2(h1);
                    rh0 = __hadd2(rh0, e0);
                    rh1 = __hadd2(rh1, e1);
                    pk[grp][j][0] = h2u(e0);
                    pk[grp][j][1] = h2u(e1);
                }
                rs[grp][0] += __low2float(rh0) + __high2float(rh0);
                rs[grp][1] += __low2float(rh1) + __high2float(rh1);
            }

            // ---- O += P_half @ STV_half : f16, B frags shared by both grps ----
#pragma unroll
            for (int kt2 = 0; kt2 < 4; kt2++) {
#pragma unroll
                for (int nbp = 0; nbp < 4; nbp++) {
                    int row = h * 64 + kt2 * 16 + ((lane >> 3) & 1) * 8 + (lane & 7);
                    int g = 2 * nbp + ((lane >> 4) & 1);
                    uint32_t b0, b1, b2, b3;
                    ldsm_x4_t(b0, b1, b2, b3, tvb + swz(row, g));
#pragma unroll
                    for (int grp = 0; grp < 2; grp++) {
                        mma_f16(o[grp][2 * nbp][0],     o[grp][2 * nbp][1],
                                pk[grp][2 * kt2][0],     pk[grp][2 * kt2][1],
                                pk[grp][2 * kt2 + 1][0], pk[grp][2 * kt2 + 1][1],
                                b0, b1);
                        mma_f16(o[grp][2 * nbp + 1][0], o[grp][2 * nbp + 1][1],
                                pk[grp][2 * kt2][0],     pk[grp][2 * kt2][1],
                                pk[grp][2 * kt2 + 1][0], pk[grp][2 * kt2 + 1][1],
                                b2, b3);
                    }
                }
            }
        }
        __syncthreads();
        if (c < 2) { load_chunk(c + 2, ksb, tvb); CP_COMMIT(); }
    }

    // ---- epilogue: rowsum reduce over lane quads, normalize, + V, store ----
#pragma unroll
    for (int grp = 0; grp < 2; grp++) {
#pragma unroll
        for (int rr = 0; rr < 2; rr++) {
            rs[grp][rr] += __shfl_xor_sync(0xffffffffu, rs[grp][rr], 1);
            rs[grp][rr] += __shfl_xor_sync(0xffffffffu, rs[grp][rr], 2);
        }
    }

    const size_t base = (size_t)bh * SEQ * DIM;
#pragma unroll
    for (int grp = 0; grp < 2; grp++) {
        const float inv0 = 1.f / rs[grp][0];
        const float inv1 = 1.f / rs[grp][1];
        const int row0 = nblk + warp * 32 + grp * 16 + (lane >> 2);
#pragma unroll
        for (int t = 0; t < 8; t++) {
            int col = t * 8 + 2 * (lane & 3);
            size_t i0 = base + (size_t)row0 * DIM + col;
            float2 p0 = __half22float2(*reinterpret_cast<__half2*>(&o[grp][t][0]));
            float2 v0 = *reinterpret_cast<const float2*>(V + i0);
            float2 w0 = make_float2(p0.x * inv0 + v0.x, p0.y * inv0 + v0.y);
            *reinterpret_cast<float2*>(out + i0) = w0;
            size_t i1 = i0 + 8 * DIM;
            float2 p1 = __half22float2(*reinterpret_cast<__half2*>(&o[grp][t][1]));
            float2 v1 = *reinterpret_cast<const float2*>(V + i1);
            float2 w1 = make_float2(p1.x * inv1 + v1.x, p1.y * inv1 + v1.y);
            *reinterpret_cast<float2*>(out + i1) = w1;
        }
    }
}

// ---------- launch ----------
extern "C" void kernel_launch(void* const* d_in, const int* in_sizes, int n_in,
                              void* d_out, int out_size) {
    const float* Q = (const float*)d_in[0];
    const float* K = (const float*)d_in[1];
    const float* V = (const float*)d_in[2];
    float* out = (float*)d_out;

    cudaFuncSetAttribute(attn_kernel, cudaFuncAttributeMaxDynamicSharedMemorySize, 65536);

    prep_kernel<<<dim3(8, BH_TOTAL), 256>>>(K, V);
    attn_kernel<<<dim3(SEQ / QROWS, BH_TOTAL), 256, 65536>>>(Q, V, out);
}

// round 6
// speedup vs baseline: 1.3869x; 1.3869x over previous
#include <cuda_runtime.h>
#include <cuda_fp16.h>
#include <stdint.h>

#define BH_TOTAL 64
#define SEQ 4096
#define DIM 64
#define M2_DIM 512
#define QROWS 256

// SKS in e4m3 (scaled by sqrt(0.125*log2e)); STV in f16
__device__ __align__(16) uint8_t g_SKS8[(size_t)BH_TOTAL * M2_DIM * DIM];
__device__ __half g_STV[(size_t)BH_TOTAL * M2_DIM * DIM];

#define QK_SCALE 0.15014065f   // sqrt(0.125 * 1.44269504)

// ---------- helpers ----------
// 128-byte smem rows, 16-byte granules, XOR swizzle
static __device__ __forceinline__ uint32_t swz(int row, int g) {
    return (uint32_t)(row * 128 + ((g ^ (row & 7)) << 4));
}
// fp8 tiles: logical 64B rows packed 2-per-128B smem row
static __device__ __forceinline__ uint32_t f8off(int row, int kb) {
    int srow = row >> 1;
    int g = ((row & 1) << 2) | kb;
    return (uint32_t)(srow * 128 + ((g ^ (srow & 7)) << 4));
}
static __device__ __forceinline__ void ldsm_x4(uint32_t& r0, uint32_t& r1, uint32_t& r2,
                                               uint32_t& r3, uint32_t addr) {
    asm volatile("ldmatrix.sync.aligned.m8n8.x4.shared.b16 {%0,%1,%2,%3}, [%4];"
                 : "=r"(r0), "=r"(r1), "=r"(r2), "=r"(r3) : "r"(addr));
}
static __device__ __forceinline__ void ldsm_x4_t(uint32_t& r0, uint32_t& r1, uint32_t& r2,
                                                 uint32_t& r3, uint32_t addr) {
    asm volatile("ldmatrix.sync.aligned.m8n8.x4.trans.shared.b16 {%0,%1,%2,%3}, [%4];"
                 : "=r"(r0), "=r"(r1), "=r"(r2), "=r"(r3) : "r"(addr));
}
// fp8 x fp8 -> f16 accum (C = 2 regs of f16x2; layout == f16 A-frag layout)
static __device__ __forceinline__ void mma_fp8h(uint32_t& c0, uint32_t& c1, const uint32_t* a,
                                                uint32_t b0, uint32_t b1) {
    asm volatile("mma.sync.aligned.m16n8k32.row.col.f16.e4m3.e4m3.f16 "
                 "{%0,%1}, {%2,%3,%4,%5}, {%6,%7}, {%0,%1};"
                 : "+r"(c0), "+r"(c1)
                 : "r"(a[0]), "r"(a[1]), "r"(a[2]), "r"(a[3]), "r"(b0), "r"(b1));
}
static __device__ __forceinline__ void mma_f16(uint32_t& c0, uint32_t& c1,
                                               uint32_t a0, uint32_t a1, uint32_t a2, uint32_t a3,
                                               uint32_t b0, uint32_t b1) {
    asm volatile("mma.sync.aligned.m16n8k16.row.col.f16.f16.f16.f16 "
                 "{%0,%1}, {%2,%3,%4,%5}, {%6,%7}, {%0,%1};"
                 : "+r"(c0), "+r"(c1)
                 : "r"(a0), "r"(a1), "r"(a2), "r"(a3), "r"(b0), "r"(b1));
}
static __device__ __forceinline__ void cp16(uint32_t dst, const void* src) {
    asm volatile("cp.async.cg.shared.global [%0], [%1], 16;" :: "r"(dst), "l"(src));
}
#define CP_COMMIT() asm volatile("cp.async.commit_group;")
static __device__ __forceinline__ uint32_t pack_e4m3_4(float x0, float x1, float x2, float x3) {
    uint16_t lo, hi;
    asm("cvt.rn.satfinite.e4m3x2.f32 %0, %1, %2;" : "=h"(lo) : "f"(x1), "f"(x0));
    asm("cvt.rn.satfinite.e4m3x2.f32 %0, %1, %2;" : "=h"(hi) : "f"(x3), "f"(x2));
    return (uint32_t)lo | ((uint32_t)hi << 16);
}
static __device__ __forceinline__ uint32_t packh(float x, float y) {
    __half2 h = __floats2half2_rn(x, y);
    return *reinterpret_cast<uint32_t*>(&h);
}
static __device__ __forceinline__ uint32_t h2u(__half2 h) {
    return *reinterpret_cast<uint32_t*>(&h);
}
static __device__ __forceinline__ __half2 u2h(uint32_t u) {
    return *reinterpret_cast<__half2*>(&u);
}

// ---------- prep: SKS (e4m3) + STV (f16), float4-vectorized ----------
// SKS[bh][m][d2] = scale * sum_j K[bh][(m&7)*512 + j*64 + d2][m>>3]
// STV[bh][m][d]  = (1/8) sum_j V[bh][8m+j][d]
__global__ __launch_bounds__(256) void prep_kernel(const float* __restrict__ K,
                                                   const float* __restrict__ V) {
    __shared__ float acc[64][65];
    const int tid = threadIdx.x;
    const int mb = blockIdx.x;   // 0..7
    const int bh = blockIdx.y;   // 0..63

    // --- transpose-accumulate 512x64 K slab (float4): acc[dk][d2] ---
    const float* Kb = K + ((size_t)bh * SEQ + (size_t)mb * 512) * DIM;
    float4 a4[4];
#pragma unroll
    for (int e = 0; e < 4; e++) a4[e] = make_float4(0.f, 0.f, 0.f, 0.f);
    for (int j = 0; j < 8; j++) {
#pragma unroll
        for (int e = 0; e < 4; e++) {
            int i = e * 256 + tid;               // 1024 float4 items (64 rows x 16)
            int r = i >> 4, c4 = i & 15;
            float4 v = reinterpret_cast<const float4*>(Kb + (size_t)(j * 64 + r) * DIM)[c4];
            a4[e].x += v.x; a4[e].y += v.y; a4[e].z += v.z; a4[e].w += v.w;
        }
    }
#pragma unroll
    for (int e = 0; e < 4; e++) {
        int i = e * 256 + tid;
        int r = i >> 4, c4 = i & 15;
        acc[c4 * 4 + 0][r] = a4[e].x;
        acc[c4 * 4 + 1][r] = a4[e].y;
        acc[c4 * 4 + 2][r] = a4[e].z;
        acc[c4 * 4 + 3][r] = a4[e].w;
    }
    __syncthreads();

    // SKS e4m3 write: thread t -> row dk = t>>2, 16 bytes at d2 = (t&3)*16
    {
        const int dk = tid >> 2;
        const int d2b = (tid & 3) * 16;
        uint8_t* dstS = g_SKS8 + (size_t)bh * M2_DIM * DIM + (size_t)(8 * dk + mb) * DIM + d2b;
        uint4 u;
        uint32_t w[4];
#pragma unroll
        for (int j = 0; j < 4; j++) {
            w[j] = pack_e4m3_4(acc[dk][d2b + 4 * j + 0] * QK_SCALE,
                               acc[dk][d2b + 4 * j + 1] * QK_SCALE,
                               acc[dk][d2b + 4 * j + 2] * QK_SCALE,
                               acc[dk][d2b + 4 * j + 3] * QK_SCALE);
        }
        u.x = w[0]; u.y = w[1]; u.z = w[2]; u.w = w[3];
        *reinterpret_cast<uint4*>(dstS) = u;
    }

    // --- STV: chunk mean of V (float4 in, f16x4 out) ---
    const float* Vb = V + (size_t)bh * SEQ * DIM;
    __half* dstV = g_STV + (size_t)bh * M2_DIM * DIM;
#pragma unroll
    for (int e = 0; e < 4; e++) {
        int i = e * 256 + tid;                   // 1024 items (64 ml x 16 d4)
        int ml = i >> 4, d4 = i & 15;
        int m = mb * 64 + ml;
        float4 s = make_float4(0.f, 0.f, 0.f, 0.f);
#pragma unroll
        for (int j = 0; j < 8; j++) {
            float4 v = reinterpret_cast<const float4*>(Vb + (size_t)(m * 8 + j) * DIM)[d4];
            s.x += v.x; s.y += v.y; s.z += v.z; s.w += v.w;
        }
        uint2 u;
        u.x = packh(s.x * 0.125f, s.y * 0.125f);
        u.y = packh(s.z * 0.125f, s.w * 0.125f);
        *reinterpret_cast<uint2*>(dstV + (size_t)m * DIM + d4 * 4) = u;
    }
}

// ---------- fused sketch attention: fp8 GEMM1 (f16 accum) + f16 GEMM2 ----------
// 256 q-rows/block, 8 warps, 32 rows/warp (2 groups of 16). m chunked 4x128.
__global__ __launch_bounds__(256, 2) void attn_kernel(const float* __restrict__ Q,
                                                      const float* __restrict__ V,
                                                      float* __restrict__ out) {
    extern __shared__ __align__(16) char smem[];
    const int tid = threadIdx.x;
    const int lane = tid & 31;
    const int warp = tid >> 5;
    const int bh = blockIdx.y;
    const int nblk = blockIdx.x * QROWS;

    const uint32_t sbase = (uint32_t)__cvta_generic_to_shared(smem);
    const uint32_t SQ  = sbase;               // 16 KB  Q fp8 (256 x 64B)
    const uint32_t KS0 = sbase + 16384;       // 8 KB   SKS fp8 chunk (128 x 64B)
    const uint32_t KS1 = sbase + 24576;
    const uint32_t TV0 = sbase + 32768;       // 16 KB  STV f16 chunk (128 x 128B)
    const uint32_t TV1 = sbase + 49152;       // total 64 KB

    const uint8_t* gKS = g_SKS8 + (size_t)bh * M2_DIM * DIM;
    const __half*  gTV = g_STV  + (size_t)bh * M2_DIM * DIM;

    auto load_chunk = [&](int c, uint32_t ksb, uint32_t tvb) {
        const char* srcK = (const char*)(gKS + (size_t)c * 128 * DIM);
        const uint4* srcV = reinterpret_cast<const uint4*>(gTV + (size_t)c * 128 * DIM);
#pragma unroll
        for (int k = 0; k < 2; k++) {         // 512 fp8 granules
            int gi = k * 256 + tid;
            int mr = gi >> 2, kb = gi & 3;
            cp16(ksb + f8off(mr, kb), srcK + gi * 16);
        }
#pragma unroll
        for (int k = 0; k < 4; k++) {         // 1024 f16 granules
            int gi = k * 256 + tid;
            int row = gi >> 3, g = gi & 7;
            cp16(tvb + swz(row, g), srcV + gi);
        }
    };

    load_chunk(0, KS0, TV0); CP_COMMIT();
    load_chunk(1, KS1, TV1); CP_COMMIT();

    // Q: fp32 -> e4m3 * QK_SCALE into swizzled smem
    {
        const float* Qb = Q + ((size_t)bh * SEQ + nblk) * DIM;
#pragma unroll
        for (int k = 0; k < 4; k++) {
            int gi = k * 256 + tid;           // 1024 granules of 16 e4m3
            int row = gi >> 2, kb = gi & 3;
            const float4* s4 = reinterpret_cast<const float4*>(Qb + (size_t)row * DIM + kb * 16);
            float4 f0 = s4[0], f1 = s4[1], f2 = s4[2], f3 = s4[3];
            uint4 u;
            u.x = pack_e4m3_4(f0.x * QK_SCALE, f0.y * QK_SCALE, f0.z * QK_SCALE, f0.w * QK_SCALE);
            u.y = pack_e4m3_4(f1.x * QK_SCALE, f1.y * QK_SCALE, f1.z * QK_SCALE, f1.w * QK_SCALE);
            u.z = pack_e4m3_4(f2.x * QK_SCALE, f2.y * QK_SCALE, f2.z * QK_SCALE, f2.w * QK_SCALE);
            u.w = pack_e4m3_4(f3.x * QK_SCALE, f3.y * QK_SCALE, f3.z * QK_SCALE, f3.w * QK_SCALE);
            *reinterpret_cast<uint4*>(smem + f8off(row, kb)) = u;
        }
    }
    __syncthreads();

    // Q A-frags (fp8 m16n8k32): per grp, 2 k32-tiles
    uint32_t qa[2][2][4];
#pragma unroll
    for (int grp = 0; grp < 2; grp++) {
#pragma unroll
        for (int kt = 0; kt < 2; kt++) {
            int row = warp * 32 + grp * 16 + ((lane >> 3) & 1) * 8 + (lane & 7);
            int kb = 2 * kt + ((lane >> 4) & 1);
            ldsm_x4(qa[grp][kt][0], qa[grp][kt][1], qa[grp][kt][2], qa[grp][kt][3],
                    SQ + f8off(row, kb));
        }
    }

    uint32_t o[2][8][2];
#pragma unroll
    for (int grp = 0; grp < 2; grp++)
#pragma unroll
        for (int t = 0; t < 8; t++) { o[grp][t][0] = 0u; o[grp][t][1] = 0u; }
    float rs[2][2] = {{0.f, 0.f}, {0.f, 0.f}};

#pragma unroll
    for (int c = 0; c < 4; c++) {
        if (c < 3) asm volatile("cp.async.wait_group 1;");
        else       asm volatile("cp.async.wait_group 0;");
        __syncthreads();
        const uint32_t ksb = (c & 1) ? KS1 : KS0;
        const uint32_t tvb = (c & 1) ? TV1 : TV0;

#pragma unroll
        for (int h = 0; h < 2; h++) {
            // ---- S = Q @ SKS_half^T (fp8, f16 accum) straight into P regs ----
            uint32_t pk[2][8][2];
#pragma unroll
            for (int grp = 0; grp < 2; grp++)
#pragma unroll
                for (int t = 0; t < 8; t++) { pk[grp][t][0] = 0u; pk[grp][t][1] = 0u; }

#pragma unroll
            for (int kt = 0; kt < 2; kt++) {
#pragma unroll
                for (int p = 0; p < 4; p++) {
                    int mr = h * 64 + p * 16 + ((lane >> 4) & 1) * 8 + (lane & 7);
                    int kb = 2 * kt + ((lane >> 3) & 1);
                    uint32_t b0, b1, b2, b3;
                    ldsm_x4(b0, b1, b2, b3, ksb + f8off(mr, kb));
#pragma unroll
                    for (int grp = 0; grp < 2; grp++) {
                        mma_fp8h(pk[grp][2 * p][0],     pk[grp][2 * p][1],     qa[grp][kt], b0, b1);
                        mma_fp8h(pk[grp][2 * p + 1][0], pk[grp][2 * p + 1][1], qa[grp][kt], b2, b3);
                    }
                }
            }

            // ---- exp2 in place (logits in log2 domain) + rowsum ----
#pragma unroll
            for (int grp = 0; grp < 2; grp++) {
                __half2 rh0 = __floats2half2_rn(0.f, 0.f);
                __half2 rh1 = rh0;
#pragma unroll
                for (int j = 0; j < 8; j++) {
                    __half2 e0 = h2exp2(u2h(pk[grp][j][0]));
                    __half2 e1 = h2exp2(u2h(pk[grp][j][1]));
                    rh0 = __hadd2(rh0, e0);
                    rh1 = __hadd2(rh1, e1);
                    pk[grp][j][0] = h2u(e0);
                    pk[grp][j][1] = h2u(e1);
                }
                rs[grp][0] += __low2float(rh0) + __high2float(rh0);
                rs[grp][1] += __low2float(rh1) + __high2float(rh1);
            }

            // ---- O += P_half @ STV_half : f16, B frags shared by both grps ----
#pragma unroll
            for (int kt2 = 0; kt2 < 4; kt2++) {
#pragma unroll
                for (int nbp = 0; nbp < 4; nbp++) {
                    int row = h * 64 + kt2 * 16 + ((lane >> 3) & 1) * 8 + (lane & 7);
                    int g = 2 * nbp + ((lane >> 4) & 1);
                    uint32_t b0, b1, b2, b3;
                    ldsm_x4_t(b0, b1, b2, b3, tvb + swz(row, g));
#pragma unroll
                    for (int grp = 0; grp < 2; grp++) {
                        mma_f16(o[grp][2 * nbp][0],     o[grp][2 * nbp][1],
                                pk[grp][2 * kt2][0],     pk[grp][2 * kt2][1],
                                pk[grp][2 * kt2 + 1][0], pk[grp][2 * kt2 + 1][1],
                                b0, b1);
                        mma_f16(o[grp][2 * nbp + 1][0], o[grp][2 * nbp + 1][1],
                                pk[grp][2 * kt2][0],     pk[grp][2 * kt2][1],
                                pk[grp][2 * kt2 + 1][0], pk[grp][2 * kt2 + 1][1],
                                b2, b3);
                    }
                }
            }
        }
        __syncthreads();
        if (c < 2) { load_chunk(c + 2, ksb, tvb); CP_COMMIT(); }
    }

    // ---- epilogue: rowsum reduce over lane quads, normalize, + V, store ----
#pragma unroll
    for (int grp = 0; grp < 2; grp++) {
#pragma unroll
        for (int rr = 0; rr < 2; rr++) {
            rs[grp][rr] += __shfl_xor_sync(0xffffffffu, rs[grp][rr], 1);
            rs[grp][rr] += __shfl_xor_sync(0xffffffffu, rs[grp][rr], 2);
        }
    }

    const size_t base = (size_t)bh * SEQ * DIM;
#pragma unroll
    for (int grp = 0; grp < 2; grp++) {
        const float inv0 = 1.f / rs[grp][0];
        const float inv1 = 1.f / rs[grp][1];
        const int row0 = nblk + warp * 32 + grp * 16 + (lane >> 2);
#pragma unroll
        for (int t = 0; t < 8; t++) {
            int col = t * 8 + 2 * (lane & 3);
            size_t i0 = base + (size_t)row0 * DIM + col;
            float2 p0 = __half22float2(u2h(o[grp][t][0]));
            float2 v0 = *reinterpret_cast<const float2*>(V + i0);
            float2 w0 = make_float2(p0.x * inv0 + v0.x, p0.y * inv0 + v0.y);
            *reinterpret_cast<float2*>(out + i0) = w0;
            size_t i1 = i0 + 8 * DIM;
            float2 p1 = __half22float2(u2h(o[grp][t][1]));
            float2 v1 = *reinterpret_cast<const float2*>(V + i1);
            float2 w1 = make_float2(p1.x * inv1 + v1.x, p1.y * inv1 + v1.y);
            *reinterpret_cast<float2*>(out + i1) = w1;
        }
    }
}

// ---------- launch ----------
extern "C" void kernel_launch(void* const* d_in, const int* in_sizes, int n_in,
                              void* d_out, int out_size) {
    const float* Q = (const float*)d_in[0];
    const float* K = (const float*)d_in[1];
    const float* V = (const float*)d_in[2];
    float* out = (float*)d_out;

    cudaFuncSetAttribute(attn_kernel, cudaFuncAttributeMaxDynamicSharedMemorySize, 65536);

    prep_kernel<<<dim3(8, BH_TOTAL), 256>>>(K, V);
    attn_kernel<<<dim3(SEQ / QROWS, BH_TOTAL), 256, 65536>>>(Q, V, out);
}